// round 1
// baseline (speedup 1.0000x reference)
#include <cuda_runtime.h>

// Problem constants (fixed shapes: B=2, H=8, S=256, d=64)
#define NB 2
#define NH 8
#define NS 256
#define ND 64
#define PER_B (NH*NS*ND)      // 131072 floats per batch in Q/V
#define OUT_HALF (NB*PER_B)   // 262144 : offset of attn in output (context first, attn second)

// W[b][u][e] = sum_{r=0..7} Q[b*131072 + u*512 + r*64 + e] * V[same],  u in [0,256)
// CP[b][c][i][e] = inclusive prefix of W over i within chunk c (u = c*64 + i)
// T[b][c][e]     = chunk total
__device__ float g_CP[NB][4][64][64];
__device__ float g_T[NB][4][64];

__global__ void __launch_bounds__(512) k_chunk_prefix(const float* __restrict__ Q,
                                                      const float* __restrict__ V) {
    int b = blockIdx.x >> 2;
    int c = blockIdx.x & 3;
    __shared__ float Wsm[64 * 64];   // [u_local][e]
    const float4* Q4 = reinterpret_cast<const float4*>(Q) + b * (PER_B / 4);
    const float4* V4 = reinterpret_cast<const float4*>(V) + b * (PER_B / 4);
    int tid = threadIdx.x;
    int ul  = tid >> 3;     // 0..63  local u
    int e4a = tid & 7;      // 0..7   float4 column (covers e4 and e4+8)
    int u   = c * 64 + ul;

    #pragma unroll
    for (int half = 0; half < 2; half++) {
        int e4 = e4a + half * 8;          // 0..15
        float4 acc = make_float4(0.f, 0.f, 0.f, 0.f);
        int base4 = u * 128 + e4;         // (u*512 + e4*4)/4
        #pragma unroll
        for (int r = 0; r < 8; r++) {
            float4 q = Q4[base4 + r * 16];
            float4 v = V4[base4 + r * 16];
            acc.x = fmaf(q.x, v.x, acc.x);
            acc.y = fmaf(q.y, v.y, acc.y);
            acc.z = fmaf(q.z, v.z, acc.z);
            acc.w = fmaf(q.w, v.w, acc.w);
        }
        int e0 = e4 * 4;
        Wsm[ul * 64 + e0 + 0] = acc.x;
        Wsm[ul * 64 + e0 + 1] = acc.y;
        Wsm[ul * 64 + e0 + 2] = acc.z;
        Wsm[ul * 64 + e0 + 3] = acc.w;
    }
    __syncthreads();

    // Serial inclusive prefix along u for each e column (64 threads, coalesced LDS).
    if (tid < 64) {
        float acc = 0.f;
        #pragma unroll 8
        for (int i = 0; i < 64; i++) {
            acc += Wsm[i * 64 + tid];
            g_CP[b][c][i][tid] = acc;
        }
        g_T[b][c][tid] = acc;
    }
}

__global__ void __launch_bounds__(256) k_attn(const float* __restrict__ V,
                                              float* __restrict__ out) {
    int warp = threadIdx.x >> 5;
    int lane = threadIdx.x & 31;
    int row  = blockIdx.x * 8 + warp;        // 0..4095 = ((b*8+h)*256+s)
    int b = row >> 11;
    int h = (row >> 8) & 7;
    int s = row & 255;

    // Circular window [base, base+63] mod 512, intersect [0,256): always 0 or 1 interval.
    int base = (((s & 7) * 64) + h * 32 + (s >> 3) + 256) & 511;

    float sc0 = 0.f, sc1 = 0.f;              // scores for e=lane, e=lane+32
    if (base < 256 || base > 448) {
        int lo, hi;
        if (base < 256) { lo = base; hi = min(base + 63, 255); }
        else            { lo = 0;    hi = base - 449; }        // wrap case
        int c0 = lo >> 6, c1 = hi >> 6;      // c1 <= c0+1
        int i0 = lo & 63, i1 = hi & 63;
        int e = lane;
        float hiA = g_CP[b][c1][i1][e];
        float hiB = g_CP[b][c1][i1][e + 32];
        float loA = (i0 > 0) ? g_CP[b][c0][i0 - 1][e]      : 0.f;
        float loB = (i0 > 0) ? g_CP[b][c0][i0 - 1][e + 32] : 0.f;
        if (c0 == c1) {
            sc0 = hiA - loA;
            sc1 = hiB - loB;
        } else {
            sc0 = (g_T[b][c0][e]      - loA) + hiA;
            sc1 = (g_T[b][c0][e + 32] - loB) + hiB;
        }
    }

    // softmax over d=64 (2 elements per lane, full-warp shuffle reduce)
    float m = fmaxf(sc0, sc1);
    #pragma unroll
    for (int d_ = 16; d_ > 0; d_ >>= 1)
        m = fmaxf(m, __shfl_xor_sync(0xffffffffu, m, d_));
    float ex0 = __expf(sc0 - m);
    float ex1 = __expf(sc1 - m);
    float ssum = ex0 + ex1;
    #pragma unroll
    for (int d_ = 16; d_ > 0; d_ >>= 1)
        ssum += __shfl_xor_sync(0xffffffffu, ssum, d_);
    float inv = __frcp_rn(ssum);

    int rowoff = row * 64;
    float a0 = ex0 * inv;
    float a1 = ex1 * inv;
    // attn second half of output, context (attn * V) first half
    out[OUT_HALF + rowoff + lane]      = a0;
    out[OUT_HALF + rowoff + lane + 32] = a1;
    out[rowoff + lane]      = a0 * V[rowoff + lane];
    out[rowoff + lane + 32] = a1 * V[rowoff + lane + 32];
}

extern "C" void kernel_launch(void* const* d_in, const int* in_sizes, int n_in,
                              void* d_out, int out_size) {
    const float* Q = (const float*)d_in[0];
    // d_in[1] (K) is genuinely unused by the reference computation.
    const float* V = (const float*)d_in[2];
    float* out = (float*)d_out;

    k_chunk_prefix<<<8, 512>>>(Q, V);
    k_attn<<<512, 256>>>(V, out);
}

// round 2
// speedup vs baseline: 1.2539x; 1.2539x over previous
#include <cuda_runtime.h>

// Fixed shapes: B=2, H=8, S=256, d=64
#define NB 2
#define NH 8
#define NS 256
#define ND 64
#define PER_B (NH*NS*ND)      // 131072 floats per batch in Q/V
#define OUT_HALF (NB*PER_B)   // 262144 floats: attn offset (context first, attn second)

// W[b][u][e] = sum_{r=0..7} Q[b*131072 + u*512 + r*64 + e] * V[same], u in [0,256)
// g_CP[b][c][i][e] = inclusive prefix of W over i within chunk c (u = c*64+i).
// Chunk total == g_CP[b][c][63][e].
__device__ float g_CP[NB][4][64][64];

// Grid 32 blocks: blk = b*16 + c*4 + eq  (eq = which 16-wide e slice)
__global__ void __launch_bounds__(256) k_chunk_prefix(const float* __restrict__ Q,
                                                      const float* __restrict__ V) {
    int blk = blockIdx.x;
    int b  = blk >> 4;
    int c  = (blk >> 2) & 3;
    int eq = blk & 3;

    __shared__ float Wsm[64][16];   // [u_local][e_local]

    int tid = threadIdx.x;
    int ul  = tid >> 2;   // 0..63
    int e4  = tid & 3;    // float4 column within the 16-e slice

    const float4* Q4 = reinterpret_cast<const float4*>(Q) + b * (PER_B / 4);
    const float4* V4 = reinterpret_cast<const float4*>(V) + b * (PER_B / 4);

    int u = c * 64 + ul;
    int base4 = u * 128 + eq * 4 + e4;   // float4 index of (u*512 + eq*16 + e4*4)

    float4 acc = make_float4(0.f, 0.f, 0.f, 0.f);
    #pragma unroll
    for (int r = 0; r < 8; r++) {
        float4 q = Q4[base4 + r * 16];
        float4 v = V4[base4 + r * 16];
        acc.x = fmaf(q.x, v.x, acc.x);
        acc.y = fmaf(q.y, v.y, acc.y);
        acc.z = fmaf(q.z, v.z, acc.z);
        acc.w = fmaf(q.w, v.w, acc.w);
    }
    *reinterpret_cast<float4*>(&Wsm[ul][e4 * 4]) = acc;
    __syncthreads();

    // Serial inclusive prefix along u for each of the 16 e-columns.
    if (tid < 16) {
        float a = 0.f;
        #pragma unroll
        for (int i = 0; i < 64; i++) {
            a += Wsm[i][tid];
            g_CP[b][c][i][eq * 16 + tid] = a;
        }
    }
}

// Grid 256 blocks x 256 threads. Each warp handles 2 rows (16 lanes/row),
// each lane covers 4 consecutive e's via float4.
__global__ void __launch_bounds__(256) k_attn(const float* __restrict__ V,
                                              float* __restrict__ out) {
    int warp = threadIdx.x >> 5;
    int lane = threadIdx.x & 31;
    int sub  = lane >> 4;       // row within warp
    int l    = lane & 15;       // e-slot: covers e = 4l .. 4l+3

    int row = blockIdx.x * 16 + warp * 2 + sub;   // 0..4095 = ((b*8+h)*256+s)
    int b = row >> 11;
    int h = (row >> 8) & 7;
    int s = row & 255;

    // Circular window [base, base+63] mod 512, intersected with [0,256):
    // always empty or a single interval.
    int base = (((s & 7) << 6) + (h << 5) + (s >> 3) + 256) & 511;

    const float4* CP4 = reinterpret_cast<const float4*>(g_CP);
    float4 sc = make_float4(0.f, 0.f, 0.f, 0.f);

    if (base < 256 || base > 448) {
        int lo, hi;
        if (base < 256) { lo = base; hi = min(base + 63, 255); }
        else            { lo = 0;    hi = base - 449; }          // wrap case
        int c0 = lo >> 6, c1 = hi >> 6;   // c1 == c0 or c0+1
        int i0 = lo & 63, i1 = hi & 63;

        // float4 index of g_CP[b][c][i][4l] = ((b*4+c)*64 + i)*16 + l
        float4 hiV = CP4[((b * 4 + c1) * 64 + i1) * 16 + l];
        float4 loV = make_float4(0.f, 0.f, 0.f, 0.f);
        if (i0 > 0) loV = CP4[((b * 4 + c0) * 64 + (i0 - 1)) * 16 + l];

        if (c0 == c1) {
            sc.x = hiV.x - loV.x;
            sc.y = hiV.y - loV.y;
            sc.z = hiV.z - loV.z;
            sc.w = hiV.w - loV.w;
        } else {
            float4 T = CP4[((b * 4 + c0) * 64 + 63) * 16 + l];  // chunk c0 total
            sc.x = (T.x - loV.x) + hiV.x;
            sc.y = (T.y - loV.y) + hiV.y;
            sc.z = (T.z - loV.z) + hiV.z;
            sc.w = (T.w - loV.w) + hiV.w;
        }
    }

    // softmax over 64 e's: 4 per lane, reduce across 16 lanes (xor 1,2,4,8
    // stays within each 16-lane half-warp).
    float m = fmaxf(fmaxf(sc.x, sc.y), fmaxf(sc.z, sc.w));
    #pragma unroll
    for (int d_ = 8; d_ > 0; d_ >>= 1)
        m = fmaxf(m, __shfl_xor_sync(0xffffffffu, m, d_));

    float e0 = __expf(sc.x - m);
    float e1 = __expf(sc.y - m);
    float e2 = __expf(sc.z - m);
    float e3 = __expf(sc.w - m);
    float ssum = (e0 + e1) + (e2 + e3);
    #pragma unroll
    for (int d_ = 8; d_ > 0; d_ >>= 1)
        ssum += __shfl_xor_sync(0xffffffffu, ssum, d_);
    float inv = __frcp_rn(ssum);

    float4 a = make_float4(e0 * inv, e1 * inv, e2 * inv, e3 * inv);

    int off4 = row * 16 + l;   // float4 index into a 64-float row
    float4 v = reinterpret_cast<const float4*>(V)[off4];

    reinterpret_cast<float4*>(out)[(OUT_HALF / 4) + off4] = a;           // attn
    reinterpret_cast<float4*>(out)[off4] =
        make_float4(a.x * v.x, a.y * v.y, a.z * v.z, a.w * v.w);         // context
}

extern "C" void kernel_launch(void* const* d_in, const int* in_sizes, int n_in,
                              void* d_out, int out_size) {
    const float* Q = (const float*)d_in[0];
    // d_in[1] (K) is genuinely unused by the reference computation.
    const float* V = (const float*)d_in[2];
    float* out = (float*)d_out;

    k_chunk_prefix<<<32, 256>>>(Q, V);
    k_attn<<<256, 256>>>(V, out);
}